// round 16
// baseline (speedup 1.0000x reference)
#include <cuda_runtime.h>
#include <math.h>
#include <stdint.h>

#define NLAYER 12
#define BATCH  4
#define SEQ    1024
#define CH     1024
#define NH     16
#define HD     64
#define MROWS  (BATCH*SEQ)   // 4096
#define LNEPS  1e-5f
#define GP     36            // gemm smem word pitch
#define BKW    32            // gemm k-chunk in words
#define KP     68            // fused-attn K/Q pitch
#define VP     132           // fused-attn V/P pitch

// ---------------- scratch (static device memory; no allocs allowed) ----------
__device__ float    g_x[MROWS*CH];
__device__ unsigned g_lns[MROWS*CH];
__device__ unsigned g_qkvs[(size_t)MROWS*3*CH];
__device__ unsigned g_vT[(size_t)BATCH*CH*SEQ];
__device__ unsigned g_y[MROWS*CH];
__device__ unsigned g_fc[(size_t)MROWS*4*CH];
__device__ unsigned g_attwT[(size_t)NLAYER*3*CH*CH];
__device__ unsigned g_projwT[(size_t)NLAYER*CH*CH];
__device__ unsigned g_fcwT[(size_t)NLAYER*4*CH*CH];
__device__ unsigned g_fc2wT[(size_t)NLAYER*4*CH*CH];

// ---------------- helpers -----------------------------------------------------
__device__ __forceinline__ unsigned splitw(float v) {          // hi | lo<<16
    unsigned u = __float_as_uint(v);
    unsigned hi = (u + 0x7fffu + ((u >> 16) & 1u)) >> 16;
    float hf = __uint_as_float(hi << 16);
    unsigned ul = __float_as_uint(v - hf);
    unsigned lo = (ul + 0x7fffu + ((ul >> 16) & 1u)) >> 16;
    return hi | (lo << 16);
}
__device__ __forceinline__ void mma_bf16(float* c, const unsigned* a, const unsigned* b) {
    asm volatile("mma.sync.aligned.m16n8k16.row.col.f32.bf16.bf16.f32 "
        "{%0,%1,%2,%3}, {%4,%5,%6,%7}, {%8,%9}, {%0,%1,%2,%3};\n"
        : "+f"(c[0]), "+f"(c[1]), "+f"(c[2]), "+f"(c[3])
        : "r"(a[0]), "r"(a[1]), "r"(a[2]), "r"(a[3]), "r"(b[0]), "r"(b[1]));
}
__device__ __forceinline__ float gelu1(float v) {
    const float kk = 0.7978845608028654f;
    return 0.5f * v * (1.f + tanhf(kk * (v + 0.044715f * v * v * v)));
}
__device__ __forceinline__ uint32_t smaddr(const void* p) {
    uint32_t u;
    asm("{ .reg .u64 t; cvta.to.shared.u64 t, %1; cvt.u32.u64 %0, t; }" : "=r"(u) : "l"(p));
    return u;
}
__device__ __forceinline__ void ldsm4(unsigned& r0, unsigned& r1, unsigned& r2,
                                      unsigned& r3, uint32_t a) {
    asm volatile("ldmatrix.sync.aligned.m8n8.x4.shared.b16 {%0,%1,%2,%3}, [%4];"
                 : "=r"(r0), "=r"(r1), "=r"(r2), "=r"(r3) : "r"(a));
}
__device__ __forceinline__ void ldsm2(unsigned& r0, unsigned& r1, uint32_t a) {
    asm volatile("ldmatrix.sync.aligned.m8n8.x2.shared.b16 {%0,%1}, [%2];"
                 : "=r"(r0), "=r"(r1) : "r"(a));
}
__device__ __forceinline__ void cpa16(uint32_t dst, const void* src) {
    asm volatile("cp.async.cg.shared.global [%0], [%1], 16;" :: "r"(dst), "l"(src));
}
__device__ __forceinline__ void cpcommit() { asm volatile("cp.async.commit_group;"); }
template<int N> __device__ __forceinline__ void cpwait() {
    asm volatile("cp.async.wait_group %0;" :: "n"(N));
}

// ---------------- copy --------------------------------------------------------
__global__ void copy_k(const float* __restrict__ in, float* __restrict__ out, int n) {
    int i = blockIdx.x * blockDim.x + threadIdx.x;
    if (i < n) out[i] = in[i];
}

// ---------------- weight split + transpose ------------------------------------
__global__ void wsplit_k(const float* __restrict__ W, unsigned* __restrict__ WT,
                         int K, int N) {
    __shared__ unsigned sm[32][33];
    const int l = blockIdx.z;
    const float* Wl = W + (size_t)l * K * N;
    unsigned* WTl = WT + (size_t)l * K * N;
    const int k0 = blockIdx.x * 32, n0 = blockIdx.y * 32;
    const int tx = threadIdx.x, ty = threadIdx.y;
    #pragma unroll
    for (int i = 0; i < 4; i++)
        sm[ty + 8*i][tx] = splitw(Wl[(size_t)(k0 + ty + 8*i) * N + n0 + tx]);
    __syncthreads();
    #pragma unroll
    for (int i = 0; i < 4; i++)
        WTl[(size_t)(n0 + ty + 8*i) * K + k0 + tx] = sm[tx][ty + 8*i];
}

// ---------------- V transpose ------------------------------------------------
__global__ void vt_k(const unsigned* __restrict__ qkvs, unsigned* __restrict__ vT) {
    __shared__ unsigned sm[32][33];
    const int b = blockIdx.z;
    const int s0 = blockIdx.x * 32, c0 = blockIdx.y * 32;
    const int tx = threadIdx.x, ty = threadIdx.y;
    #pragma unroll
    for (int i = 0; i < 4; i++)
        sm[ty + 8*i][tx] = qkvs[(size_t)(b * SEQ + s0 + ty + 8*i) * (3*CH) + 2*CH + c0 + tx];
    __syncthreads();
    #pragma unroll
    for (int i = 0; i < 4; i++)
        vT[(size_t)(b * CH + c0 + ty + 8*i) * SEQ + s0 + tx] = sm[tx][ty + 8*i];
}

// ---------------- layernorm --------------------------------------------------
template<bool SPLIT>
__global__ void ln_k(const float* __restrict__ in, const float* __restrict__ gam,
                     const float* __restrict__ bet, void* __restrict__ outv) {
    int row = blockIdx.x;
    const float* p = in + (size_t)row * CH;
    float s = 0.f, s2 = 0.f;
    for (int c = threadIdx.x; c < CH; c += blockDim.x) {
        float v = p[c];
        s += v; s2 += v * v;
    }
    __shared__ float sh[16];
    #pragma unroll
    for (int o = 16; o > 0; o >>= 1) {
        s  += __shfl_down_sync(0xffffffffu, s, o);
        s2 += __shfl_down_sync(0xffffffffu, s2, o);
    }
    int lane = threadIdx.x & 31, w = threadIdx.x >> 5;
    if (lane == 0) { sh[w] = s; sh[8 + w] = s2; }
    __syncthreads();
    if (threadIdx.x == 0) {
        float a = 0.f, b = 0.f;
        #pragma unroll
        for (int i = 0; i < 8; i++) { a += sh[i]; b += sh[8 + i]; }
        sh[0] = a; sh[8] = b;
    }
    __syncthreads();
    float mean = sh[0] * (1.f / CH);
    float var  = sh[8] * (1.f / CH) - mean * mean;
    float rstd = rsqrtf(var + LNEPS);
    for (int c = threadIdx.x; c < CH; c += blockDim.x) {
        float v = (p[c] - mean) * rstd * gam[c] + bet[c];
        if (SPLIT) ((unsigned*)outv)[(size_t)row * CH + c] = splitw(v);
        else       ((float*)outv)[(size_t)row * CH + c] = v;
    }
}

// ---------------- bf16 compensated GEMM, 3-stage + warp-staggered c-loop -----
#define SA_ST (128*GP)
#define GSMEM (3*2*SA_ST*4)   // 110592 B

template<bool DO_GELU, bool DO_RES, bool OUT_SPLIT>
__global__ void __launch_bounds__(256, 2) gemmbf(
    const unsigned* __restrict__ A, const unsigned* __restrict__ Bt,
    const float* __restrict__ bias, const float* __restrict__ Res,
    void* __restrict__ Cv, int N, int K)
{
    extern __shared__ unsigned sm[];
    unsigned* As = sm;                 // [3][128][GP]
    unsigned* Bs = sm + 3 * SA_ST;
    const int tid = threadIdx.x;
    const int row0 = blockIdx.y * 128, col0 = blockIdx.x * 128;
    const int warp = tid >> 5, lane = tid & 31;
    const int wm = warp >> 2, wn = warp & 3;
    const int g = lane >> 2, tg = lane & 3;
    const int ldr = tid >> 3, ldc = (tid & 7) << 2;
    const int cst = warp & 3;          // per-warp c-phase stagger (desync stalls)

    float acc[4][4][4] = {};

    const int arow = lane & 15, asel = (lane >> 4) << 2;
    const int brow = lane & 7,  bsel = ((lane >> 3) & 1) << 2;

    auto load_stage = [&](int s, int kw) {
        unsigned* Ad = As + s * SA_ST;
        unsigned* Bd = Bs + s * SA_ST;
        #pragma unroll
        for (int j = 0; j < 4; j++) {
            int r = ldr + j * 32;
            cpa16(smaddr(Ad + r * GP + ldc), A  + (size_t)(row0 + r) * K + kw + ldc);
        }
        #pragma unroll
        for (int j = 0; j < 4; j++) {
            int r = ldr + j * 32;
            cpa16(smaddr(Bd + r * GP + ldc), Bt + (size_t)(col0 + r) * K + kw + ldc);
        }
        cpcommit();
    };

    load_stage(0, 0);
    load_stage(1, BKW);

    const int nk = K >> 5;
    int s = 0;
    for (int kt = 0; kt < nk; kt++) {
        cpwait<1>();
        __syncthreads();
        const unsigned* Ab = As + s * SA_ST;
        const unsigned* Bb = Bs + s * SA_ST;
        #pragma unroll
        for (int ci = 0; ci < 4; ci++) {
            const int c = (ci + cst) & 3;      // staggered phase per warp
            const int cw = c * 8;
            unsigned af[4][4];
            #pragma unroll
            for (int mi = 0; mi < 4; mi++) {
                const int m0 = wm * 64 + mi * 16;
                ldsm4(af[mi][0], af[mi][1], af[mi][2], af[mi][3],
                      smaddr(Ab + (m0 + arow) * GP + cw + asel));
            }
            #pragma unroll
            for (int nh = 0; nh < 2; nh++) {
                unsigned bd[2][2], bl[2][2];
                #pragma unroll
                for (int u = 0; u < 2; u++) {
                    const int n0 = (wn * 4 + nh * 2 + u) * 8;
                    unsigned w0, w1;
                    ldsm2(w0, w1, smaddr(Bb + (n0 + brow) * GP + cw + bsel));
                    bd[u][0] = __byte_perm(w0, w0, 0x1010);
                    bd[u][1] = __byte_perm(w1, w1, 0x1010);
                    bl[u][0] = w0 >> 16;
                    bl[u][1] = w1 >> 16;
                }
                #pragma unroll
                for (int u = 0; u < 2; u++)
                    #pragma unroll
                    for (int mi = 0; mi < 4; mi++)
                        mma_bf16(acc[mi][nh * 2 + u], af[mi], bd[u]);
                #pragma unroll
                for (int u = 0; u < 2; u++)
                    #pragma unroll
                    for (int mi = 0; mi < 4; mi++)
                        mma_bf16(acc[mi][nh * 2 + u], af[mi], bl[u]);
            }
        }
        if (kt + 2 < nk) {
            int ns = s + 2; if (ns >= 3) ns -= 3;
            load_stage(ns, (kt + 2) * BKW);
        } else {
            cpcommit();   // empty group keeps cpwait<1> accounting exact on tail
        }
        if (++s == 3) s = 0;
    }

    // epilogue
    #pragma unroll
    for (int mi = 0; mi < 4; mi++) {
        #pragma unroll
        for (int p = 0; p < 2; p++) {
            const size_t r = (size_t)(row0 + wm * 64 + mi * 16 + g + p * 8);
            #pragma unroll
            for (int ni = 0; ni < 4; ni++) {
                const int col = col0 + wn * 32 + ni * 8 + 2 * tg;
                float2 bv = *(const float2*)(bias + col);
                float v0 = acc[mi][ni][2*p+0] + bv.x;
                float v1 = acc[mi][ni][2*p+1] + bv.y;
                if (DO_GELU) { v0 = gelu1(v0); v1 = gelu1(v1); }
                if (DO_RES) {
                    float2 rv = *(const float2*)(Res + r * N + col);
                    v0 += rv.x; v1 += rv.y;
                }
                if (OUT_SPLIT)
                    *(uint2*)((unsigned*)Cv + r * N + col) =
                        make_uint2(splitw(v0), splitw(v1));
                else
                    *(float2*)((float*)Cv + r * N + col) = make_float2(v0, v1);
            }
        }
    }
}

// ---------------- fused flash attention (round-15 proven) --------------------
#define FKS_ST (128*KP)
#define FVS_ST (64*VP)
#define FSMEM ((2*FKS_ST + 2*FVS_ST + 128*VP)*4)   // 204800 B

__global__ void __launch_bounds__(256, 1) attn_fused(
    const unsigned* __restrict__ qkvs, const unsigned* __restrict__ vT,
    unsigned* __restrict__ y)
{
    extern __shared__ unsigned fsm[];
    unsigned* Ks = fsm;                         // [2][128][KP]
    unsigned* Vs = fsm + 2*FKS_ST;              // [2][64][VP]
    unsigned* Ps = fsm + 2*FKS_ST + 2*FVS_ST;   // [128][VP]; Q staged here (pitch KP)
    const int bh = blockIdx.y, b = bh >> 4, h = bh & 15;
    const int qt = (int)gridDim.x - 1 - (int)blockIdx.x;
    const int tid = threadIdx.x;
    const int warp = tid >> 5, lane = tid & 31;
    const int g = lane >> 2, tg = lane & 3;
    const int arow = lane & 15, asel = (lane >> 4) << 2;
    const int brow = lane & 7,  bsel = ((lane >> 3) & 1) << 2;
    const size_t RS = 3 * CH;
    const unsigned* Qb = qkvs + (size_t)(b*SEQ + qt*128) * RS + h*HD;
    const unsigned* Kb = qkvs + (size_t)(b*SEQ) * RS + CH + h*HD;
    const unsigned* Vb = vT + (size_t)bh * HD * SEQ;

    auto load_kv = [&](int s, int kt) {
        unsigned* Kd = Ks + s * FKS_ST;
        unsigned* Vd = Vs + s * FVS_ST;
        const unsigned* Kg = Kb + (size_t)(kt * 128) * RS;
        #pragma unroll
        for (int j = 0; j < 8; j++) {
            int idx = tid + j * 256;
            int r = idx >> 4, c4 = (idx & 15) << 2;
            cpa16(smaddr(Kd + r * KP + c4), Kg + (size_t)r * RS + c4);
        }
        #pragma unroll
        for (int j = 0; j < 8; j++) {
            int idx = tid + j * 256;
            int r = idx >> 5, c4 = (idx & 31) << 2;
            cpa16(smaddr(Vd + r * VP + c4), Vb + (size_t)r * SEQ + kt * 128 + c4);
        }
        cpcommit();
    };

    #pragma unroll
    for (int j = 0; j < 8; j++) {
        int idx = tid + j * 256;
        int r = idx >> 4, c4 = (idx & 15) << 2;
        cpa16(smaddr(Ps + r * KP + c4), Qb + (size_t)r * RS + c4);
    }
    cpcommit();
    load_kv(0, 0);
    cpwait<0>();
    __syncthreads();
    unsigned qf[8][4];
    #pragma unroll
    for (int c = 0; c < 8; c++)
        ldsm4(qf[c][0], qf[c][1], qf[c][2], qf[c][3],
              smaddr(Ps + (warp * 16 + arow) * KP + c * 8 + asel));
    __syncthreads();

    float oacc[8][4] = {};
    float M0 = -1e30f, M1 = -1e30f, l0 = 0.f, l1 = 0.f;
    const int q0 = qt * 128 + warp * 16 + g;
    const int q1 = q0 + 8;

    for (int kt = 0; kt <= qt; kt++) {
        const int s = kt & 1;
        if (kt > 0) { cpwait<0>(); __syncthreads(); }
        if (kt < qt) load_kv(s ^ 1, kt + 1);
        const unsigned* Kc = Ks + s * FKS_ST;
        const unsigned* Vc = Vs + s * FVS_ST;

        float sacc[16][4];
        #pragma unroll
        for (int i = 0; i < 16; i++) {
            sacc[i][0] = 0.f; sacc[i][1] = 0.f; sacc[i][2] = 0.f; sacc[i][3] = 0.f;
        }
        #pragma unroll
        for (int c = 0; c < 8; c++) {
            const int cw = c * 8;
            #pragma unroll
            for (int nb = 0; nb < 4; nb++) {
                unsigned wv[4][2];
                #pragma unroll
                for (int u = 0; u < 4; u++)
                    ldsm2(wv[u][0], wv[u][1],
                          smaddr(Kc + ((nb * 4 + u) * 8 + brow) * KP + cw + bsel));
                #pragma unroll
                for (int u = 0; u < 4; u++) {
                    unsigned bd[2] = { __byte_perm(wv[u][0], wv[u][0], 0x1010),
                                       __byte_perm(wv[u][1], wv[u][1], 0x1010) };
                    mma_bf16(sacc[nb * 4 + u], qf[c], bd);
                }
                #pragma unroll
                for (int u = 0; u < 4; u++) {
                    unsigned bl[2] = { wv[u][0] >> 16, wv[u][1] >> 16 };
                    mma_bf16(sacc[nb * 4 + u], qf[c], bl);
                }
            }
        }
        const bool diag = (kt == qt);
        float mx0 = -1e30f, mx1 = -1e30f;
        #pragma unroll
        for (int ni = 0; ni < 16; ni++) {
            float s0 = sacc[ni][0] * 0.125f, s1 = sacc[ni][1] * 0.125f;
            float s2 = sacc[ni][2] * 0.125f, s3 = sacc[ni][3] * 0.125f;
            if (diag) {
                int k0 = kt * 128 + ni * 8 + 2 * tg;
                if (k0     > q0) s0 = -1e30f;
                if (k0 + 1 > q0) s1 = -1e30f;
                if (k0     > q1) s2 = -1e30f;
                if (k0 + 1 > q1) s3 = -1e30f;
            }
            sacc[ni][0] = s0; sacc[ni][1] = s1; sacc[ni][2] = s2; sacc[ni][3] = s3;
            mx0 = fmaxf(mx0, fmaxf(s0, s1));
            mx1 = fmaxf(mx1, fmaxf(s2, s3));
        }
        mx0 = fmaxf(mx0, __shfl_xor_sync(0xffffffffu, mx0, 1));
        mx0 = fmaxf(mx0, __shfl_xor_sync(0xffffffffu, mx0, 2));
        mx1 = fmaxf(mx1, __shfl_xor_sync(0xffffffffu, mx1, 1));
        mx1 = fmaxf(mx1, __shfl_xor_sync(0xffffffffu, mx1, 2));
        const float M0n = fmaxf(M0, mx0), M1n = fmaxf(M1, mx1);
        const float sc0 = __expf(M0 - M0n), sc1 = __expf(M1 - M1n);
        M0 = M0n; M1 = M1n;
        float rs0 = 0.f, rs1 = 0.f;
        unsigned* Prow0 = Ps + (warp * 16 + g) * VP + 2 * tg;
        unsigned* Prow1 = Prow0 + 8 * VP;
        #pragma unroll
        for (int ni = 0; ni < 16; ni++) {
            float p0 = __expf(sacc[ni][0] - M0n);
            float p1 = __expf(sacc[ni][1] - M0n);
            float p2 = __expf(sacc[ni][2] - M1n);
            float p3 = __expf(sacc[ni][3] - M1n);
            rs0 += p0 + p1; rs1 += p2 + p3;
            *(uint2*)(Prow0 + ni * 8) = make_uint2(splitw(p0), splitw(p1));
            *(uint2*)(Prow1 + ni * 8) = make_uint2(splitw(p2), splitw(p3));
        }
        rs0 += __shfl_xor_sync(0xffffffffu, rs0, 1);
        rs0 += __shfl_xor_sync(0xffffffffu, rs0, 2);
        rs1 += __shfl_xor_sync(0xffffffffu, rs1, 1);
        rs1 += __shfl_xor_sync(0xffffffffu, rs1, 2);
        l0 = l0 * sc0 + rs0;
        l1 = l1 * sc1 + rs1;
        #pragma unroll
        for (int no = 0; no < 8; no++) {
            oacc[no][0] *= sc0; oacc[no][1] *= sc0;
            oacc[no][2] *= sc1; oacc[no][3] *= sc1;
        }
        __syncwarp();
        #pragma unroll
        for (int c2 = 0; c2 < 16; c2++) {
            const int cw = c2 * 8;
            unsigned af[4];
            ldsm4(af[0], af[1], af[2], af[3],
                  smaddr(Ps + (warp * 16 + arow) * VP + cw + asel));
            #pragma unroll
            for (int nb = 0; nb < 2; nb++) {
                unsigned wv[4][2];
                #pragma unroll
                for (int u = 0; u < 4; u++)
                    ldsm2(wv[u][0], wv[u][1],
                          smaddr(Vc + ((nb * 4 + u) * 8 + brow) * VP + cw + bsel));
                #pragma unroll
                for (int u = 0; u < 4; u++) {
                    unsigned bd[2] = { __byte_perm(wv[u][0], wv[u][0], 0x1010),
                                       __byte_perm(wv[u][1], wv[u][1], 0x1010) };
                    mma_bf16(oacc[nb * 4 + u], af, bd);
                }
                #pragma unroll
                for (int u = 0; u < 4; u++) {
                    unsigned bl[2] = { wv[u][0] >> 16, wv[u][1] >> 16 };
                    mma_bf16(oacc[nb * 4 + u], af, bl);
                }
            }
        }
        __syncwarp();
    }
    const float inv0 = 1.f / l0, inv1 = 1.f / l1;
    const size_t r0 = (size_t)(b * SEQ + qt * 128 + warp * 16 + g);
    #pragma unroll
    for (int no = 0; no < 8; no++) {
        const int col = h * HD + no * 8 + 2 * tg;
        *(uint2*)(y + r0 * CH + col) =
            make_uint2(splitw(oacc[no][0] * inv0), splitw(oacc[no][1] * inv0));
        *(uint2*)(y + (r0 + 8) * CH + col) =
            make_uint2(splitw(oacc[no][2] * inv1), splitw(oacc[no][3] * inv1));
    }
}

// ---------------- host launcher ----------------------------------------------
extern "C" void kernel_launch(void* const* d_in, const int* in_sizes, int n_in,
                              void* d_out, int out_size)
{
    const float* x     = (const float*)d_in[0];
    const float* ln1g  = (const float*)d_in[1];
    const float* ln1b  = (const float*)d_in[2];
    const float* attw  = (const float*)d_in[3];
    const float* attb  = (const float*)d_in[4];
    const float* projw = (const float*)d_in[5];
    const float* projb = (const float*)d_in[6];
    const float* ln2g  = (const float*)d_in[7];
    const float* ln2b  = (const float*)d_in[8];
    const float* fcw   = (const float*)d_in[9];
    const float* fcb   = (const float*)d_in[10];
    const float* fc2w  = (const float*)d_in[11];
    const float* fc2b  = (const float*)d_in[12];
    const float* lnfg  = (const float*)d_in[13];
    const float* lnfb  = (const float*)d_in[14];

    float *px;
    unsigned *plns, *pqkvs, *pvT, *py, *pfc;
    unsigned *pattwT, *pprojwT, *pfcwT, *pfc2wT;
    cudaGetSymbolAddress((void**)&px,      g_x);
    cudaGetSymbolAddress((void**)&plns,    g_lns);
    cudaGetSymbolAddress((void**)&pqkvs,   g_qkvs);
    cudaGetSymbolAddress((void**)&pvT,     g_vT);
    cudaGetSymbolAddress((void**)&py,      g_y);
    cudaGetSymbolAddress((void**)&pfc,     g_fc);
    cudaGetSymbolAddress((void**)&pattwT,  g_attwT);
    cudaGetSymbolAddress((void**)&pprojwT, g_projwT);
    cudaGetSymbolAddress((void**)&pfcwT,   g_fcwT);
    cudaGetSymbolAddress((void**)&pfc2wT,  g_fc2wT);

    cudaFuncSetAttribute(gemmbf<false, false, true>,
                         cudaFuncAttributeMaxDynamicSharedMemorySize, GSMEM);
    cudaFuncSetAttribute(gemmbf<false, true, false>,
                         cudaFuncAttributeMaxDynamicSharedMemorySize, GSMEM);
    cudaFuncSetAttribute(gemmbf<true, false, true>,
                         cudaFuncAttributeMaxDynamicSharedMemorySize, GSMEM);
    cudaFuncSetAttribute(attn_fused,
                         cudaFuncAttributeMaxDynamicSharedMemorySize, FSMEM);

    const dim3 t32x8(32, 8);

    // launch index 3 = qkv gemm (ncu -s 5 capture slot)
    copy_k<<<(MROWS * CH + 255) / 256, 256>>>(x, px, MROWS * CH);                      // 0
    wsplit_k<<<dim3(CH/32, 3*CH/32, NLAYER), t32x8>>>(attw,  pattwT,  CH,   3*CH);     // 1
    ln_k<true><<<MROWS, 256>>>(px, ln1g, ln1b, plns);                                  // 2
    gemmbf<false, false, true><<<dim3(3 * CH / 128, MROWS / 128), 256, GSMEM>>>(       // 3
        plns, pattwT, attb, nullptr, pqkvs, 3 * CH, CH);
    wsplit_k<<<dim3(CH/32,   CH/32, NLAYER), t32x8>>>(projw, pprojwT, CH,   CH);       // 4
    wsplit_k<<<dim3(CH/32, 4*CH/32, NLAYER), t32x8>>>(fcw,   pfcwT,   CH,   4*CH);     // 5
    wsplit_k<<<dim3(4*CH/32, CH/32, NLAYER), t32x8>>>(fc2w,  pfc2wT,  4*CH, CH);       // 6

    for (int l = 0; l < NLAYER; l++) {
        if (l > 0) {
            ln_k<true><<<MROWS, 256>>>(px, ln1g + l * CH, ln1b + l * CH, plns);
            gemmbf<false, false, true><<<dim3(3 * CH / 128, MROWS / 128), 256, GSMEM>>>(
                plns, pattwT + (size_t)l * 3 * CH * CH, attb + (size_t)l * 3 * CH,
                nullptr, pqkvs, 3 * CH, CH);
        }
        vt_k<<<dim3(SEQ/32, CH/32, BATCH), t32x8>>>(pqkvs, pvT);
        attn_fused<<<dim3(SEQ/128, BATCH * NH), 256, FSMEM>>>(pqkvs, pvT, py);
        gemmbf<false, true, false><<<dim3(CH / 128, MROWS / 128), 256, GSMEM>>>(
            py, pprojwT + (size_t)l * CH * CH, projb + (size_t)l * CH,
            px, px, CH, CH);
        ln_k<true><<<MROWS, 256>>>(px, ln2g + l * CH, ln2b + l * CH, plns);
        gemmbf<true, false, true><<<dim3(4 * CH / 128, MROWS / 128), 256, GSMEM>>>(
            plns, pfcwT + (size_t)l * 4 * CH * CH, fcb + (size_t)l * 4 * CH,
            nullptr, pfc, 4 * CH, CH);
        gemmbf<false, true, false><<<dim3(CH / 128, MROWS / 128), 256, GSMEM>>>(
            pfc, pfc2wT + (size_t)l * 4 * CH * CH, fc2b + (size_t)l * CH,
            px, px, CH, 4 * CH);
    }
    ln_k<false><<<MROWS, 256>>>(px, lnfg, lnfb, (float*)d_out);
}

// round 17
// speedup vs baseline: 1.0432x; 1.0432x over previous
#include <cuda_runtime.h>
#include <math.h>
#include <stdint.h>

#define NLAYER 12
#define BATCH  4
#define SEQ    1024
#define CH     1024
#define NH     16
#define HD     64
#define MROWS  (BATCH*SEQ)   // 4096
#define LNEPS  1e-5f
#define GP     36            // gemm smem word pitch
#define BKW    32            // gemm k-chunk in words
#define KP     68            // fused-attn K/Q pitch
#define VP     132           // fused-attn V/P pitch

// ---------------- scratch (static device memory; no allocs allowed) ----------
__device__ float    g_x[MROWS*CH];
__device__ unsigned g_lns[MROWS*CH];
__device__ unsigned g_qkvs[(size_t)MROWS*3*CH];
__device__ unsigned g_vT[(size_t)BATCH*CH*SEQ];
__device__ unsigned g_y[MROWS*CH];
__device__ unsigned g_fc[(size_t)MROWS*4*CH];
__device__ unsigned g_attwT[(size_t)NLAYER*3*CH*CH];
__device__ unsigned g_projwT[(size_t)NLAYER*CH*CH];
__device__ unsigned g_fcwT[(size_t)NLAYER*4*CH*CH];
__device__ unsigned g_fc2wT[(size_t)NLAYER*4*CH*CH];

// ---------------- helpers -----------------------------------------------------
__device__ __forceinline__ unsigned splitw(float v) {          // hi | lo<<16
    unsigned u = __float_as_uint(v);
    unsigned hi = (u + 0x7fffu + ((u >> 16) & 1u)) >> 16;
    float hf = __uint_as_float(hi << 16);
    unsigned ul = __float_as_uint(v - hf);
    unsigned lo = (ul + 0x7fffu + ((ul >> 16) & 1u)) >> 16;
    return hi | (lo << 16);
}
__device__ __forceinline__ void mma_bf16(float* c, const unsigned* a, const unsigned* b) {
    asm volatile("mma.sync.aligned.m16n8k16.row.col.f32.bf16.bf16.f32 "
        "{%0,%1,%2,%3}, {%4,%5,%6,%7}, {%8,%9}, {%0,%1,%2,%3};\n"
        : "+f"(c[0]), "+f"(c[1]), "+f"(c[2]), "+f"(c[3])
        : "r"(a[0]), "r"(a[1]), "r"(a[2]), "r"(a[3]), "r"(b[0]), "r"(b[1]));
}
__device__ __forceinline__ float gelu1(float v) {
    const float kk = 0.7978845608028654f;
    return 0.5f * v * (1.f + tanhf(kk * (v + 0.044715f * v * v * v)));
}
__device__ __forceinline__ uint32_t smaddr(const void* p) {
    uint32_t u;
    asm("{ .reg .u64 t; cvta.to.shared.u64 t, %1; cvt.u32.u64 %0, t; }" : "=r"(u) : "l"(p));
    return u;
}
__device__ __forceinline__ void ldsm4(unsigned& r0, unsigned& r1, unsigned& r2,
                                      unsigned& r3, uint32_t a) {
    asm volatile("ldmatrix.sync.aligned.m8n8.x4.shared.b16 {%0,%1,%2,%3}, [%4];"
                 : "=r"(r0), "=r"(r1), "=r"(r2), "=r"(r3) : "r"(a));
}
__device__ __forceinline__ void ldsm2(unsigned& r0, unsigned& r1, uint32_t a) {
    asm volatile("ldmatrix.sync.aligned.m8n8.x2.shared.b16 {%0,%1}, [%2];"
                 : "=r"(r0), "=r"(r1) : "r"(a));
}
__device__ __forceinline__ void cpa16(uint32_t dst, const void* src) {
    asm volatile("cp.async.cg.shared.global [%0], [%1], 16;" :: "r"(dst), "l"(src));
}
__device__ __forceinline__ void cpcommit() { asm volatile("cp.async.commit_group;"); }
template<int N> __device__ __forceinline__ void cpwait() {
    asm volatile("cp.async.wait_group %0;" :: "n"(N));
}
// ---- mbarrier primitives (cp.async pipeline) ----
__device__ __forceinline__ void mbar_init(uint32_t a, uint32_t c) {
    asm volatile("mbarrier.init.shared.b64 [%0], %1;" :: "r"(a), "r"(c) : "memory");
}
__device__ __forceinline__ void mbar_arrive(uint32_t a) {
    asm volatile("mbarrier.arrive.shared.b64 _, [%0];" :: "r"(a) : "memory");
}
__device__ __forceinline__ void cp_arrive(uint32_t a) {
    asm volatile("cp.async.mbarrier.arrive.noinc.shared.b64 [%0];" :: "r"(a) : "memory");
}
__device__ __forceinline__ void mbar_wait(uint32_t a, uint32_t parity) {
    asm volatile(
        "{\n\t.reg .pred P;\n\t"
        "W_%=:\n\t"
        "mbarrier.try_wait.parity.acquire.cta.shared::cta.b64 P, [%0], %1, 0x989680;\n\t"
        "@P bra.uni D_%=;\n\t"
        "bra.uni W_%=;\n\t"
        "D_%=:\n\t}"
        :: "r"(a), "r"(parity) : "memory");
}

// ---------------- copy --------------------------------------------------------
__global__ void copy_k(const float* __restrict__ in, float* __restrict__ out, int n) {
    int i = blockIdx.x * blockDim.x + threadIdx.x;
    if (i < n) out[i] = in[i];
}

// ---------------- weight split + transpose ------------------------------------
__global__ void wsplit_k(const float* __restrict__ W, unsigned* __restrict__ WT,
                         int K, int N) {
    __shared__ unsigned sm[32][33];
    const int l = blockIdx.z;
    const float* Wl = W + (size_t)l * K * N;
    unsigned* WTl = WT + (size_t)l * K * N;
    const int k0 = blockIdx.x * 32, n0 = blockIdx.y * 32;
    const int tx = threadIdx.x, ty = threadIdx.y;
    #pragma unroll
    for (int i = 0; i < 4; i++)
        sm[ty + 8*i][tx] = splitw(Wl[(size_t)(k0 + ty + 8*i) * N + n0 + tx]);
    __syncthreads();
    #pragma unroll
    for (int i = 0; i < 4; i++)
        WTl[(size_t)(n0 + ty + 8*i) * K + k0 + tx] = sm[tx][ty + 8*i];
}

// ---------------- V transpose ------------------------------------------------
__global__ void vt_k(const unsigned* __restrict__ qkvs, unsigned* __restrict__ vT) {
    __shared__ unsigned sm[32][33];
    const int b = blockIdx.z;
    const int s0 = blockIdx.x * 32, c0 = blockIdx.y * 32;
    const int tx = threadIdx.x, ty = threadIdx.y;
    #pragma unroll
    for (int i = 0; i < 4; i++)
        sm[ty + 8*i][tx] = qkvs[(size_t)(b * SEQ + s0 + ty + 8*i) * (3*CH) + 2*CH + c0 + tx];
    __syncthreads();
    #pragma unroll
    for (int i = 0; i < 4; i++)
        vT[(size_t)(b * CH + c0 + ty + 8*i) * SEQ + s0 + tx] = sm[tx][ty + 8*i];
}

// ---------------- layernorm --------------------------------------------------
template<bool SPLIT>
__global__ void ln_k(const float* __restrict__ in, const float* __restrict__ gam,
                     const float* __restrict__ bet, void* __restrict__ outv) {
    int row = blockIdx.x;
    const float* p = in + (size_t)row * CH;
    float s = 0.f, s2 = 0.f;
    for (int c = threadIdx.x; c < CH; c += blockDim.x) {
        float v = p[c];
        s += v; s2 += v * v;
    }
    __shared__ float sh[16];
    #pragma unroll
    for (int o = 16; o > 0; o >>= 1) {
        s  += __shfl_down_sync(0xffffffffu, s, o);
        s2 += __shfl_down_sync(0xffffffffu, s2, o);
    }
    int lane = threadIdx.x & 31, w = threadIdx.x >> 5;
    if (lane == 0) { sh[w] = s; sh[8 + w] = s2; }
    __syncthreads();
    if (threadIdx.x == 0) {
        float a = 0.f, b = 0.f;
        #pragma unroll
        for (int i = 0; i < 8; i++) { a += sh[i]; b += sh[8 + i]; }
        sh[0] = a; sh[8] = b;
    }
    __syncthreads();
    float mean = sh[0] * (1.f / CH);
    float var  = sh[8] * (1.f / CH) - mean * mean;
    float rstd = rsqrtf(var + LNEPS);
    for (int c = threadIdx.x; c < CH; c += blockDim.x) {
        float v = (p[c] - mean) * rstd * gam[c] + bet[c];
        if (SPLIT) ((unsigned*)outv)[(size_t)row * CH + c] = splitw(v);
        else       ((float*)outv)[(size_t)row * CH + c] = v;
    }
}

// ---------------- bf16 compensated GEMM, 3-stage mbarrier pipeline -----------
#define SA_ST (128*GP)
#define GSMEM (3*2*SA_ST*4)   // 110592 B

template<bool DO_GELU, bool DO_RES, bool OUT_SPLIT>
__global__ void __launch_bounds__(256, 2) gemmbf(
    const unsigned* __restrict__ A, const unsigned* __restrict__ Bt,
    const float* __restrict__ bias, const float* __restrict__ Res,
    void* __restrict__ Cv, int N, int K)
{
    extern __shared__ unsigned sm[];
    __shared__ uint64_t mbars[6];      // full[0..2], empty[3..5]
    unsigned* As = sm;                 // [3][128][GP]
    unsigned* Bs = sm + 3 * SA_ST;
    const int tid = threadIdx.x;
    const int row0 = blockIdx.y * 128, col0 = blockIdx.x * 128;
    const int warp = tid >> 5, lane = tid & 31;
    const int wm = warp >> 2, wn = warp & 3;
    const int g = lane >> 2, tg = lane & 3;
    const int ldr = tid >> 3, ldc = (tid & 7) << 2;

    const uint32_t mb = smaddr(mbars);
    if (tid == 0) {
        #pragma unroll
        for (int j = 0; j < 6; j++) mbar_init(mb + j * 8, 256);
    }
    __syncthreads();

    float acc[4][4][4] = {};

    const int arow = lane & 15, asel = (lane >> 4) << 2;
    const int brow = lane & 7,  bsel = ((lane >> 3) & 1) << 2;

    auto load_stage = [&](int s, int kw) {
        unsigned* Ad = As + s * SA_ST;
        unsigned* Bd = Bs + s * SA_ST;
        #pragma unroll
        for (int j = 0; j < 4; j++) {
            int r = ldr + j * 32;
            cpa16(smaddr(Ad + r * GP + ldc), A  + (size_t)(row0 + r) * K + kw + ldc);
        }
        #pragma unroll
        for (int j = 0; j < 4; j++) {
            int r = ldr + j * 32;
            cpa16(smaddr(Bd + r * GP + ldc), Bt + (size_t)(col0 + r) * K + kw + ldc);
        }
        cp_arrive(mb + s * 8);         // full[s] fires when this thread's fills land
    };

    load_stage(0, 0);
    load_stage(1, BKW);

    const int nk = K >> 5;
    int s = 0;
    for (int kt = 0; kt < nk; kt++) {
        // consumer: wait stage s full (fill index kt/3, parity of it)
        mbar_wait(mb + s * 8, ((unsigned)kt / 3u) & 1u);
        const unsigned* Ab = As + s * SA_ST;
        const unsigned* Bb = Bs + s * SA_ST;
        #pragma unroll
        for (int c = 0; c < 4; c++) {
            const int cw = c * 8;
            unsigned af[4][4];
            #pragma unroll
            for (int mi = 0; mi < 4; mi++) {
                const int m0 = wm * 64 + mi * 16;
                ldsm4(af[mi][0], af[mi][1], af[mi][2], af[mi][3],
                      smaddr(Ab + (m0 + arow) * GP + cw + asel));
            }
            #pragma unroll
            for (int nh = 0; nh < 2; nh++) {
                unsigned bd[2][2], bl[2][2];
                #pragma unroll
                for (int u = 0; u < 2; u++) {
                    const int n0 = (wn * 4 + nh * 2 + u) * 8;
                    unsigned w0, w1;
                    ldsm2(w0, w1, smaddr(Bb + (n0 + brow) * GP + cw + bsel));
                    bd[u][0] = __byte_perm(w0, w0, 0x1010);
                    bd[u][1] = __byte_perm(w1, w1, 0x1010);
                    bl[u][0] = w0 >> 16;
                    bl[u][1] = w1 >> 16;
                }
                #pragma unroll
                for (int u = 0; u < 2; u++)
                    #pragma unroll
                    for (int mi = 0; mi < 4; mi++)
                        mma_bf16(acc[mi][nh * 2 + u], af[mi], bd[u]);
                #pragma unroll
                for (int u = 0; u < 2; u++)
                    #pragma unroll
                    for (int mi = 0; mi < 4; mi++)
                        mma_bf16(acc[mi][nh * 2 + u], af[mi], bl[u]);
            }
        }
        mbar_arrive(mb + 24 + s * 8);  // done reading stage s
        if (kt + 2 < nk) {
            int j = s + 2; if (j >= 3) j -= 3;
            unsigned f2 = ((unsigned)(kt + 2)) / 3u;   // fill index for stage j
            if (f2 >= 1) mbar_wait(mb + 24 + j * 8, (f2 - 1u) & 1u);
            load_stage(j, (kt + 2) * BKW);
        }
        if (++s == 3) s = 0;
    }

    // epilogue
    #pragma unroll
    for (int mi = 0; mi < 4; mi++) {
        #pragma unroll
        for (int p = 0; p < 2; p++) {
            const size_t r = (size_t)(row0 + wm * 64 + mi * 16 + g + p * 8);
            #pragma unroll
            for (int ni = 0; ni < 4; ni++) {
                const int col = col0 + wn * 32 + ni * 8 + 2 * tg;
                float2 bv = *(const float2*)(bias + col);
                float v0 = acc[mi][ni][2*p+0] + bv.x;
                float v1 = acc[mi][ni][2*p+1] + bv.y;
                if (DO_GELU) { v0 = gelu1(v0); v1 = gelu1(v1); }
                if (DO_RES) {
                    float2 rv = *(const float2*)(Res + r * N + col);
                    v0 += rv.x; v1 += rv.y;
                }
                if (OUT_SPLIT)
                    *(uint2*)((unsigned*)Cv + r * N + col) =
                        make_uint2(splitw(v0), splitw(v1));
                else
                    *(float2*)((float*)Cv + r * N + col) = make_float2(v0, v1);
            }
        }
    }
}

// ---------------- fused flash attention (round-15 proven) --------------------
#define FKS_ST (128*KP)
#define FVS_ST (64*VP)
#define FSMEM ((2*FKS_ST + 2*FVS_ST + 128*VP)*4)   // 204800 B

__global__ void __launch_bounds__(256, 1) attn_fused(
    const unsigned* __restrict__ qkvs, const unsigned* __restrict__ vT,
    unsigned* __restrict__ y)
{
    extern __shared__ unsigned fsm[];
    unsigned* Ks = fsm;                         // [2][128][KP]
    unsigned* Vs = fsm + 2*FKS_ST;              // [2][64][VP]
    unsigned* Ps = fsm + 2*FKS_ST + 2*FVS_ST;   // [128][VP]; Q staged here (pitch KP)
    const int bh = blockIdx.y, b = bh >> 4, h = bh & 15;
    const int qt = (int)gridDim.x - 1 - (int)blockIdx.x;
    const int tid = threadIdx.x;
    const int warp = tid >> 5, lane = tid & 31;
    const int g = lane >> 2, tg = lane & 3;
    const int arow = lane & 15, asel = (lane >> 4) << 2;
    const int brow = lane & 7,  bsel = ((lane >> 3) & 1) << 2;
    const size_t RS = 3 * CH;
    const unsigned* Qb = qkvs + (size_t)(b*SEQ + qt*128) * RS + h*HD;
    const unsigned* Kb = qkvs + (size_t)(b*SEQ) * RS + CH + h*HD;
    const unsigned* Vb = vT + (size_t)bh * HD * SEQ;

    auto load_kv = [&](int s, int kt) {
        unsigned* Kd = Ks + s * FKS_ST;
        unsigned* Vd = Vs + s * FVS_ST;
        const unsigned* Kg = Kb + (size_t)(kt * 128) * RS;
        #pragma unroll
        for (int j = 0; j < 8; j++) {
            int idx = tid + j * 256;
            int r = idx >> 4, c4 = (idx & 15) << 2;
            cpa16(smaddr(Kd + r * KP + c4), Kg + (size_t)r * RS + c4);
        }
        #pragma unroll
        for (int j = 0; j < 8; j++) {
            int idx = tid + j * 256;
            int r = idx >> 5, c4 = (idx & 31) << 2;
            cpa16(smaddr(Vd + r * VP + c4), Vb + (size_t)r * SEQ + kt * 128 + c4);
        }
        cpcommit();
    };

    #pragma unroll
    for (int j = 0; j < 8; j++) {
        int idx = tid + j * 256;
        int r = idx >> 4, c4 = (idx & 15) << 2;
        cpa16(smaddr(Ps + r * KP + c4), Qb + (size_t)r * RS + c4);
    }
    cpcommit();
    load_kv(0, 0);
    cpwait<0>();
    __syncthreads();
    unsigned qf[8][4];
    #pragma unroll
    for (int c = 0; c < 8; c++)
        ldsm4(qf[c][0], qf[c][1], qf[c][2], qf[c][3],
              smaddr(Ps + (warp * 16 + arow) * KP + c * 8 + asel));
    __syncthreads();

    float oacc[8][4] = {};
    float M0 = -1e30f, M1 = -1e30f, l0 = 0.f, l1 = 0.f;
    const int q0 = qt * 128 + warp * 16 + g;
    const int q1 = q0 + 8;

    for (int kt = 0; kt <= qt; kt++) {
        const int s = kt & 1;
        if (kt > 0) { cpwait<0>(); __syncthreads(); }
        if (kt < qt) load_kv(s ^ 1, kt + 1);
        const unsigned* Kc = Ks + s * FKS_ST;
        const unsigned* Vc = Vs + s * FVS_ST;

        float sacc[16][4];
        #pragma unroll
        for (int i = 0; i < 16; i++) {
            sacc[i][0] = 0.f; sacc[i][1] = 0.f; sacc[i][2] = 0.f; sacc[i][3] = 0.f;
        }
        #pragma unroll
        for (int c = 0; c < 8; c++) {
            const int cw = c * 8;
            #pragma unroll
            for (int nb = 0; nb < 4; nb++) {
                unsigned wv[4][2];
                #pragma unroll
                for (int u = 0; u < 4; u++)
                    ldsm2(wv[u][0], wv[u][1],
                          smaddr(Kc + ((nb * 4 + u) * 8 + brow) * KP + cw + bsel));
                #pragma unroll
                for (int u = 0; u < 4; u++) {
                    unsigned bd[2] = { __byte_perm(wv[u][0], wv[u][0], 0x1010),
                                       __byte_perm(wv[u][1], wv[u][1], 0x1010) };
                    mma_bf16(sacc[nb * 4 + u], qf[c], bd);
                }
                #pragma unroll
                for (int u = 0; u < 4; u++) {
                    unsigned bl[2] = { wv[u][0] >> 16, wv[u][1] >> 16 };
                    mma_bf16(sacc[nb * 4 + u], qf[c], bl);
                }
            }
        }
        const bool diag = (kt == qt);
        float mx0 = -1e30f, mx1 = -1e30f;
        #pragma unroll
        for (int ni = 0; ni < 16; ni++) {
            float s0 = sacc[ni][0] * 0.125f, s1 = sacc[ni][1] * 0.125f;
            float s2 = sacc[ni][2] * 0.125f, s3 = sacc[ni][3] * 0.125f;
            if (diag) {
                int k0 = kt * 128 + ni * 8 + 2 * tg;
                if (k0     > q0) s0 = -1e30f;
                if (k0 + 1 > q0) s1 = -1e30f;
                if (k0     > q1) s2 = -1e30f;
                if (k0 + 1 > q1) s3 = -1e30f;
            }
            sacc[ni][0] = s0; sacc[ni][1] = s1; sacc[ni][2] = s2; sacc[ni][3] = s3;
            mx0 = fmaxf(mx0, fmaxf(s0, s1));
            mx1 = fmaxf(mx1, fmaxf(s2, s3));
        }
        mx0 = fmaxf(mx0, __shfl_xor_sync(0xffffffffu, mx0, 1));
        mx0 = fmaxf(mx0, __shfl_xor_sync(0xffffffffu, mx0, 2));
        mx1 = fmaxf(mx1, __shfl_xor_sync(0xffffffffu, mx1, 1));
        mx1 = fmaxf(mx1, __shfl_xor_sync(0xffffffffu, mx1, 2));
        const float M0n = fmaxf(M0, mx0), M1n = fmaxf(M1, mx1);
        const float sc0 = __expf(M0 - M0n), sc1 = __expf(M1 - M1n);
        M0 = M0n; M1 = M1n;
        float rs0 = 0.f, rs1 = 0.f;
        unsigned* Prow0 = Ps + (warp * 16 + g) * VP + 2 * tg;
        unsigned* Prow1 = Prow0 + 8 * VP;
        #pragma unroll
        for (int ni = 0; ni < 16; ni++) {
            float p0 = __expf(sacc[ni][0] - M0n);
            float p1 = __expf(sacc[ni][1] - M0n);
            float p2 = __expf(sacc[ni][2] - M1n);
            float p3 = __expf(sacc[ni][3] - M1n);
            rs0 += p0 + p1; rs1 += p2 + p3;
            *(uint2*)(Prow0 + ni * 8) = make_uint2(splitw(p0), splitw(p1));
            *(uint2*)(Prow1 + ni * 8) = make_uint2(splitw(p2), splitw(p3));
        }
        rs0 += __shfl_xor_sync(0xffffffffu, rs0, 1);
        rs0 += __shfl_xor_sync(0xffffffffu, rs0, 2);
        rs1 += __shfl_xor_sync(0xffffffffu, rs1, 1);
        rs1 += __shfl_xor_sync(0xffffffffu, rs1, 2);
        l0 = l0 * sc0 + rs0;
        l1 = l1 * sc1 + rs1;
        #pragma unroll
        for (int no = 0; no < 8; no++) {
            oacc[no][0] *= sc0; oacc[no][1] *= sc0;
            oacc[no][2] *= sc1; oacc[no][3] *= sc1;
        }
        __syncwarp();
        #pragma unroll
        for (int c2 = 0; c2 < 16; c2++) {
            const int cw = c2 * 8;
            unsigned af[4];
            ldsm4(af[0], af[1], af[2], af[3],
                  smaddr(Ps + (warp * 16 + arow) * VP + cw + asel));
            #pragma unroll
            for (int nb = 0; nb < 2; nb++) {
                unsigned wv[4][2];
                #pragma unroll
                for (int u = 0; u < 4; u++)
                    ldsm2(wv[u][0], wv[u][1],
                          smaddr(Vc + ((nb * 4 + u) * 8 + brow) * VP + cw + bsel));
                #pragma unroll
                for (int u = 0; u < 4; u++) {
                    unsigned bd[2] = { __byte_perm(wv[u][0], wv[u][0], 0x1010),
                                       __byte_perm(wv[u][1], wv[u][1], 0x1010) };
                    mma_bf16(oacc[nb * 4 + u], af, bd);
                }
                #pragma unroll
                for (int u = 0; u < 4; u++) {
                    unsigned bl[2] = { wv[u][0] >> 16, wv[u][1] >> 16 };
                    mma_bf16(oacc[nb * 4 + u], af, bl);
                }
            }
        }
        __syncwarp();
    }
    const float inv0 = 1.f / l0, inv1 = 1.f / l1;
    const size_t r0 = (size_t)(b * SEQ + qt * 128 + warp * 16 + g);
    #pragma unroll
    for (int no = 0; no < 8; no++) {
        const int col = h * HD + no * 8 + 2 * tg;
        *(uint2*)(y + r0 * CH + col) =
            make_uint2(splitw(oacc[no][0] * inv0), splitw(oacc[no][1] * inv0));
        *(uint2*)(y + (r0 + 8) * CH + col) =
            make_uint2(splitw(oacc[no][2] * inv1), splitw(oacc[no][3] * inv1));
    }
}

// ---------------- host launcher ----------------------------------------------
extern "C" void kernel_launch(void* const* d_in, const int* in_sizes, int n_in,
                              void* d_out, int out_size)
{
    const float* x     = (const float*)d_in[0];
    const float* ln1g  = (const float*)d_in[1];
    const float* ln1b  = (const float*)d_in[2];
    const float* attw  = (const float*)d_in[3];
    const float* attb  = (const float*)d_in[4];
    const float* projw = (const float*)d_in[5];
    const float* projb = (const float*)d_in[6];
    const float* ln2g  = (const float*)d_in[7];
    const float* ln2b  = (const float*)d_in[8];
    const float* fcw   = (const float*)d_in[9];
    const float* fcb   = (const float*)d_in[10];
    const float* fc2w  = (const float*)d_in[11];
    const float* fc2b  = (const float*)d_in[12];
    const float* lnfg  = (const float*)d_in[13];
    const float* lnfb  = (const float*)d_in[14];

    float *px;
    unsigned *plns, *pqkvs, *pvT, *py, *pfc;
    unsigned *pattwT, *pprojwT, *pfcwT, *pfc2wT;
    cudaGetSymbolAddress((void**)&px,      g_x);
    cudaGetSymbolAddress((void**)&plns,    g_lns);
    cudaGetSymbolAddress((void**)&pqkvs,   g_qkvs);
    cudaGetSymbolAddress((void**)&pvT,     g_vT);
    cudaGetSymbolAddress((void**)&py,      g_y);
    cudaGetSymbolAddress((void**)&pfc,     g_fc);
    cudaGetSymbolAddress((void**)&pattwT,  g_attwT);
    cudaGetSymbolAddress((void**)&pprojwT, g_projwT);
    cudaGetSymbolAddress((void**)&pfcwT,   g_fcwT);
    cudaGetSymbolAddress((void**)&pfc2wT,  g_fc2wT);

    cudaFuncSetAttribute(gemmbf<false, false, true>,
                         cudaFuncAttributeMaxDynamicSharedMemorySize, GSMEM);
    cudaFuncSetAttribute(gemmbf<false, true, false>,
                         cudaFuncAttributeMaxDynamicSharedMemorySize, GSMEM);
    cudaFuncSetAttribute(gemmbf<true, false, true>,
                         cudaFuncAttributeMaxDynamicSharedMemorySize, GSMEM);
    cudaFuncSetAttribute(attn_fused,
                         cudaFuncAttributeMaxDynamicSharedMemorySize, FSMEM);

    const dim3 t32x8(32, 8);

    // launch index 3 = qkv gemm (ncu -s 5 capture slot)
    copy_k<<<(MROWS * CH + 255) / 256, 256>>>(x, px, MROWS * CH);                      // 0
    wsplit_k<<<dim3(CH/32, 3*CH/32, NLAYER), t32x8>>>(attw,  pattwT,  CH,   3*CH);     // 1
    ln_k<true><<<MROWS, 256>>>(px, ln1g, ln1b, plns);                                  // 2
    gemmbf<false, false, true><<<dim3(3 * CH / 128, MROWS / 128), 256, GSMEM>>>(       // 3
        plns, pattwT, attb, nullptr, pqkvs, 3 * CH, CH);
    wsplit_k<<<dim3(CH/32,   CH/32, NLAYER), t32x8>>>(projw, pprojwT, CH,   CH);       // 4
    wsplit_k<<<dim3(CH/32, 4*CH/32, NLAYER), t32x8>>>(fcw,   pfcwT,   CH,   4*CH);     // 5
    wsplit_k<<<dim3(4*CH/32, CH/32, NLAYER), t32x8>>>(fc2w,  pfc2wT,  4*CH, CH);       // 6

    for (int l = 0; l < NLAYER; l++) {
        if (l > 0) {
            ln_k<true><<<MROWS, 256>>>(px, ln1g + l * CH, ln1b + l * CH, plns);
            gemmbf<false, false, true><<<dim3(3 * CH / 128, MROWS / 128), 256, GSMEM>>>(
                plns, pattwT + (size_t)l * 3 * CH * CH, attb + (size_t)l * 3 * CH,
                nullptr, pqkvs, 3 * CH, CH);
        }
        vt_k<<<dim3(SEQ/32, CH/32, BATCH), t32x8>>>(pqkvs, pvT);
        attn_fused<<<dim3(SEQ/128, BATCH * NH), 256, FSMEM>>>(pqkvs, pvT, py);
        gemmbf<false, true, false><<<dim3(CH / 128, MROWS / 128), 256, GSMEM>>>(
            py, pprojwT + (size_t)l * CH * CH, projb + (size_t)l * CH,
            px, px, CH, CH);
        ln_k<true><<<MROWS, 256>>>(px, ln2g + l * CH, ln2b + l * CH, plns);
        gemmbf<true, false, true><<<dim3(4 * CH / 128, MROWS / 128), 256, GSMEM>>>(
            plns, pfcwT + (size_t)l * 4 * CH * CH, fcb + (size_t)l * 4 * CH,
            nullptr, pfc, 4 * CH, CH);
        gemmbf<false, true, false><<<dim3(CH / 128, MROWS / 128), 256, GSMEM>>>(
            pfc, pfc2wT + (size_t)l * 4 * CH * CH, fc2b + (size_t)l * CH,
            px, px, CH, 4 * CH);
    }
    ln_k<false><<<MROWS, 256>>>(px, lnfg, lnfb, (float*)d_out);
}